// round 17
// baseline (speedup 1.0000x reference)
#include <cuda_runtime.h>
#include <cuda_bf16.h>
#include <cstdint>
#include <math.h>

#define C 256
#define NPOS 32768
#define G 8
#define H 4

// ---- scratch --------------------------------------------------------------
__device__ float g_tokens[2 * C * G];          // [b][c][g]
__device__ float g_V[2 * H * G * 64];          // [b][h][g][d]
__device__ __nv_bfloat16 g_B1h[2 * 32 * 256];  // [b][hg][c]  Ms~^T hi
__device__ __nv_bfloat16 g_B1l[2 * 32 * 256];  // [b][hg][c]  Ms~^T lo
__device__ __nv_bfloat16 g_B2h[2 * 256 * 32];  // [b][o][hg]  P^T hi
__device__ __nv_bfloat16 g_B2l[2 * 256 * 32];  // [b][o][hg]  P^T lo
__device__ float g_cs[2 * 32];                 // colsum of Ms~
__device__ float g_bias[2 * 32];               // Ms_raw . nq_b

// ---- helpers ----------------------------------------------------------------
__device__ __forceinline__ uint32_t smem_to_u32(const void* p) {
    uint32_t a;
    asm("{ .reg .u64 t; cvta.to.shared.u64 t, %1; cvt.u32.u64 %0, t; }"
        : "=r"(a) : "l"(p));
    return a;
}
__device__ __forceinline__ void cpa16(unsigned s, const void* g) {
    asm volatile("cp.async.cg.shared.global [%0], [%1], 16;" :: "r"(s), "l"(g));
}
__device__ __forceinline__ void cpa_commit() { asm volatile("cp.async.commit_group;"); }
__device__ __forceinline__ void cpa_wait1() { asm volatile("cp.async.wait_group 1;"); }
__device__ __forceinline__ void cpa_wait0() { asm volatile("cp.async.wait_group 0;"); }

__device__ __forceinline__ uint32_t bf16pack(float lo, float hi) {
    uint32_t r;
    asm("cvt.rn.bf16x2.f32 %0, %1, %2;" : "=r"(r) : "f"(hi), "f"(lo));
    return r;
}
__device__ __forceinline__ void mma16816(float* d, const uint32_t* a, const uint32_t* b) {
    asm volatile(
        "mma.sync.aligned.m16n8k16.row.col.f32.bf16.bf16.f32 "
        "{%0,%1,%2,%3}, {%4,%5,%6,%7}, {%8,%9}, {%0,%1,%2,%3};"
        : "+f"(d[0]), "+f"(d[1]), "+f"(d[2]), "+f"(d[3])
        : "r"(a[0]), "r"(a[1]), "r"(a[2]), "r"(a[3]), "r"(b[0]), "r"(b[1]));
}

// ---------------------------------------------------------------------------
// pool 16^3 -> 2^3 + depthwise conv + residual. grid 256, 2 channels/block.
// ---------------------------------------------------------------------------
__global__ void k_tokens(const float* __restrict__ x1,
                         const float* __restrict__ dw_w) {
    int bc0 = blockIdx.x * 2;
    int tid = threadIdx.x;
    int w = tid >> 5, lane = tid & 31;
    int gz = w >> 2, gy = (w >> 1) & 1, gx = w & 1;
    __shared__ float pooled[2][8];
    float s[2] = {0.f, 0.f};
#pragma unroll
    for (int cc = 0; cc < 2; cc++) {
        const float* xp = x1 + (size_t)(bc0 + cc) * 4096;
#pragma unroll
        for (int p = 0; p < 2; p++) {
            int idx = lane + p * 32;
            int lz = idx >> 3, ly = idx & 7;
            const float4* r = reinterpret_cast<const float4*>(
                xp + (gz * 8 + lz) * 256 + (gy * 8 + ly) * 16 + gx * 8);
            float4 a = r[0], b4 = r[1];
            s[cc] += a.x + a.y + a.z + a.w + b4.x + b4.y + b4.z + b4.w;
        }
    }
#pragma unroll
    for (int off = 16; off; off >>= 1) {
        s[0] += __shfl_down_sync(0xffffffffu, s[0], off);
        s[1] += __shfl_down_sync(0xffffffffu, s[1], off);
    }
    if (lane == 0) {
        pooled[0][w] = s[0] * (1.0f / 512.0f);
        pooled[1][w] = s[1] * (1.0f / 512.0f);
    }
    __syncthreads();
    int cz = w >> 2, cy = (w >> 1) & 1, cx = w & 1;
    float val[2] = {0.f, 0.f};
    if (lane < 27) {
        int dz = lane / 9 - 1, dy = (lane / 3) % 3 - 1, dx = lane % 3 - 1;
        int nz = cz + dz, ny = cy + dy, nx = cx + dx;
        if ((unsigned)nz < 2u && (unsigned)ny < 2u && (unsigned)nx < 2u) {
            int pi = nz * 4 + ny * 2 + nx;
            val[0] = dw_w[(bc0 & 255) * 27 + lane] * pooled[0][pi];
            val[1] = dw_w[((bc0 + 1) & 255) * 27 + lane] * pooled[1][pi];
        }
    }
#pragma unroll
    for (int off = 16; off; off >>= 1) {
        val[0] += __shfl_down_sync(0xffffffffu, val[0], off);
        val[1] += __shfl_down_sync(0xffffffffu, val[1], off);
    }
    if (lane == 0) {
        g_tokens[bc0 * 8 + w] = pooled[0][w] + val[0];
        g_tokens[(bc0 + 1) * 8 + w] = pooled[1][w] + val[1];
    }
}

// ---------------------------------------------------------------------------
// k_kvf: grid 64 = b*32 + h*8 + g. LN(token) -> kd/vd (head h) -> B1 row,
// cs/bias, g_V for foldB. (g_K round-trip eliminated.)
// ---------------------------------------------------------------------------
__global__ void k_kvf(const float* __restrict__ k_w, const float* __restrict__ v_w,
                      const float* __restrict__ q_w,
                      const float* __restrict__ nkv_w, const float* __restrict__ nkv_b,
                      const float* __restrict__ nq_w, const float* __restrict__ nq_b) {
    int bid = blockIdx.x;
    int b = bid >> 5, hg = bid & 31, h = hg >> 3, g = hg & 7;
    int tid = threadIdx.x;
    int w = tid >> 5, lane = tid & 31;
    __shared__ float tok[256], tk[256], kd[64], red[16];
    __shared__ float uu, rstd;
    float t = g_tokens[(b * 256 + tid) * 8 + g];
    tok[tid] = t;
    float s1 = t, s2 = t * t;
#pragma unroll
    for (int off = 16; off; off >>= 1) {
        s1 += __shfl_down_sync(0xffffffffu, s1, off);
        s2 += __shfl_down_sync(0xffffffffu, s2, off);
    }
    if (lane == 0) { red[w] = s1; red[8 + w] = s2; }
    __syncthreads();
    if (tid == 0) {
        float a = 0.f, qq = 0.f;
        for (int i = 0; i < 8; i++) { a += red[i]; qq += red[8 + i]; }
        float u = a * (1.0f / 256.0f);
        float var = qq * (1.0f / 256.0f) - u * u;
        uu = u; rstd = rsqrtf(var + 1e-6f);
    }
    __syncthreads();
    tk[tid] = (t - uu) * rstd * nkv_w[tid] + nkv_b[tid];
    __syncthreads();
    // kd/vd for head h: warp w -> d = w*8..w*8+7
#pragma unroll
    for (int oo = 0; oo < 8; oo++) {
        int d = w * 8 + oo;
        int o = h * 64 + d;
        const float* kr = k_w + o * 256;
        const float* vr = v_w + o * 256;
        float pk = 0.f, pv = 0.f;
#pragma unroll
        for (int i = 0; i < 8; i++) {
            int c2 = lane + 32 * i;
            pk += kr[c2] * tk[c2];
            pv += vr[c2] * tok[c2];
        }
#pragma unroll
        for (int off = 16; off; off >>= 1) {
            pk += __shfl_down_sync(0xffffffffu, pk, off);
            pv += __shfl_down_sync(0xffffffffu, pv, off);
        }
        if (lane == 0) {
            kd[d] = pk * 0.125f;
            g_V[((b * 4 + h) * 8 + g) * 64 + d] = pv;
        }
    }
    __syncthreads();
    // B1 row hg: thread = c
    {
        float s = 0.f;
        const float* qp = q_w + (h * 64) * 256 + tid;
#pragma unroll 8
        for (int d = 0; d < 64; d++) s += qp[d * 256] * kd[d];
        float sp = s * nq_w[tid];
        float sb = s * nq_b[tid];
        __nv_bfloat16 hb = __float2bfloat16(sp);
        g_B1h[b * 8192 + hg * 256 + tid] = hb;
        g_B1l[b * 8192 + hg * 256 + tid] = __float2bfloat16(sp - __bfloat162float(hb));
        float a1 = sp, a2 = sb;
#pragma unroll
        for (int off = 16; off; off >>= 1) {
            a1 += __shfl_down_sync(0xffffffffu, a1, off);
            a2 += __shfl_down_sync(0xffffffffu, a2, off);
        }
        if (lane == 0) { red[w] = a1; red[8 + w] = a2; }
    }
    __syncthreads();
    if (tid == 0) {
        float c1 = 0.f, c2 = 0.f;
        for (int i = 0; i < 8; i++) { c1 += red[i]; c2 += red[8 + i]; }
        g_cs[b * 32 + hg] = c1;
        g_bias[b * 32 + hg] = c2;
    }
}

// ---------------------------------------------------------------------------
// foldB: B2 = P^T hi/lo. grid 256 = (b,hg,quarter); 8 rows/warp.
// ---------------------------------------------------------------------------
__global__ void k_foldB(const float* __restrict__ proj_w) {
    int bid = blockIdx.x;
    int q = bid & 3;
    int bhg = bid >> 2;
    int b = bhg >> 5, hg = bhg & 31, h = hg >> 3, g = hg & 7;
    int tid = threadIdx.x;
    int w = tid >> 5, lane = tid & 31;
    __shared__ float vd[64];
    if (tid < 64) vd[tid] = g_V[((b * 4 + h) * 8 + g) * 64 + tid];
    __syncthreads();
#pragma unroll
    for (int oo = 0; oo < 8; oo++) {
        int o = q * 64 + w * 8 + oo;
        const float* pw = proj_w + o * 256 + h * 64;
        float p = pw[lane] * vd[lane] + pw[32 + lane] * vd[32 + lane];
#pragma unroll
        for (int off = 16; off; off >>= 1)
            p += __shfl_down_sync(0xffffffffu, p, off);
        if (lane == 0) {
            __nv_bfloat16 hb = __float2bfloat16(p);
            g_B2h[b * 8192 + o * 32 + hg] = hb;
            g_B2l[b * 8192 + o * 32 + hg] = __float2bfloat16(p - __bfloat162float(hb));
        }
    }
}

// ---------------------------------------------------------------------------
// main kernel v8 (r16 + B-fragment hoisting, kb-outer loop):
// 256 positions/block, 256 threads, grid 256. 8 chunks x 32 channels.
// smem (bytes), time-multiplexed:
//  X 0..66560 (2 x 32ch x 260f) -> B2H@0 (256x80) B2L@20480 after mainloop
//  B1 66560..100352 -> stage(32x260f) in GEMM2
//  CS 100352 | BIAS 100480 | TOT 100608
// ---------------------------------------------------------------------------
#define SB_XS   0
#define SB_B2H  0
#define SB_B2L  20480
#define SB_R2   66560
#define SB_B1H  66560
#define SB_B1L  83456
#define SB_CS   100352
#define SB_BIAS 100480
#define SB_TOT  100608

__global__ void __launch_bounds__(256, 2) k_main(
    const float* __restrict__ x2, float* __restrict__ out) {
    extern __shared__ char smc[];
    uint32_t smb = smem_to_u32(smc);
    int tid = threadIdx.x;
    int lane = tid & 31, w = tid >> 5;
    int g = lane >> 2, tg = lane & 3;
    int b = blockIdx.x >> 7;
    int n0 = (blockIdx.x & 127) * 256;
    const float* xb = x2 + (size_t)b * (C * NPOS) + n0;

    // ---- prologue: B1 (group 0), X chunk 0 (group 1), cs/bias
    {
        const char* s1 = (const char*)g_B1h + b * 16384;
        const char* s2 = (const char*)g_B1l + b * 16384;
        for (int i = tid; i < 1024; i += 256) {
            int r = i >> 5, c2 = i & 31;
            cpa16(smb + SB_B1H + r * 528 + c2 * 16, s1 + r * 512 + c2 * 16);
            cpa16(smb + SB_B1L + r * 528 + c2 * 16, s2 + r * 512 + c2 * 16);
        }
        cpa_commit();
        for (int i = tid; i < 2048; i += 256) {
            int r = i >> 6, c2 = i & 63;
            cpa16(smb + SB_XS + r * 1040 + c2 * 16, xb + (size_t)r * NPOS + c2 * 4);
        }
        cpa_commit();
        if (tid < 32) ((float*)(smc + SB_CS))[tid] = g_cs[b * 32 + tid];
        else if (tid < 64) ((float*)(smc + SB_BIAS))[tid - 32] = g_bias[b * 32 + tid - 32];
    }

    const uint32_t* b1h = (const uint32_t*)(smc + SB_B1H);
    const uint32_t* b1l = (const uint32_t*)(smc + SB_B1L);
    float d1[2][4][4] = {};
    float s1v[2][2] = {}, s2v[2][2] = {};

    for (int ch = 0; ch < 8; ch++) {
        if (ch < 7) {
            const float* src = xb + (size_t)((ch + 1) * 32) * NPOS;
            unsigned dst = smb + SB_XS + ((unsigned)((ch + 1) & 1)) * 33280u;
            for (int i = tid; i < 2048; i += 256) {
                int r = i >> 6, c2 = i & 63;
                cpa16(dst + r * 1040 + c2 * 16, src + (size_t)r * NPOS + c2 * 4);
            }
            cpa_commit();
            cpa_wait1();
        } else {
            cpa_wait0();
        }
        __syncthreads();
        const float* Xb = (const float*)(smc + SB_XS + ((ch & 1) ? 33280u : 0u));

#pragma unroll
        for (int kb = 0; kb < 2; kb++) {
            // hoisted B1 fragments (independent of t)
            int kidx = ch * 16 + kb * 8 + tg;
            uint32_t BH[4][2], BL[4][2];
#pragma unroll
            for (int nb = 0; nb < 4; nb++) {
                int n = nb * 8 + g;
                BH[nb][0] = b1h[n * 132 + kidx];
                BH[nb][1] = b1h[n * 132 + kidx + 4];
                BL[nb][0] = b1l[n * 132 + kidx];
                BL[nb][1] = b1l[n * 132 + kidx + 4];
            }
            int k0 = kb * 16 + 2 * tg;
#pragma unroll
            for (int t = 0; t < 2; t++) {
                int m0 = w * 32 + t * 16 + g;
                float f[8];
                f[0] = Xb[k0 * 260 + m0];           f[1] = Xb[(k0 + 1) * 260 + m0];
                f[2] = Xb[k0 * 260 + m0 + 8];       f[3] = Xb[(k0 + 1) * 260 + m0 + 8];
                f[4] = Xb[(k0 + 8) * 260 + m0];     f[5] = Xb[(k0 + 9) * 260 + m0];
                f[6] = Xb[(k0 + 8) * 260 + m0 + 8]; f[7] = Xb[(k0 + 9) * 260 + m0 + 8];
                s1v[t][0] += f[0] + f[1] + f[4] + f[5];
                s1v[t][1] += f[2] + f[3] + f[6] + f[7];
                s2v[t][0] += f[0] * f[0] + f[1] * f[1] + f[4] * f[4] + f[5] * f[5];
                s2v[t][1] += f[2] * f[2] + f[3] * f[3] + f[6] * f[6] + f[7] * f[7];
                uint32_t ah[4], al[4];
#pragma unroll
                for (int qd = 0; qd < 4; qd++) {
                    uint32_t hp = bf16pack(f[2 * qd], f[2 * qd + 1]);
                    float r0 = f[2 * qd]     - __uint_as_float(hp << 16);
                    float r1 = f[2 * qd + 1] - __uint_as_float(hp & 0xffff0000u);
                    ah[qd] = hp;
                    al[qd] = bf16pack(r0, r1);
                }
#pragma unroll
                for (int nb = 0; nb < 4; nb++) {
                    mma16816(d1[t][nb], ah, BH[nb]);
                    mma16816(d1[t][nb], al, BH[nb]);
                    mma16816(d1[t][nb], ah, BL[nb]);
                }
            }
        }
        __syncthreads();   // all warps done with this buffer before next prefetch
    }

    // ---- B2 into dead X region (async, overlapped with register epilogue)
    {
        const char* s3 = (const char*)g_B2h + b * 16384;
        const char* s4 = (const char*)g_B2l + b * 16384;
        for (int i = tid; i < 1024; i += 256) {
            int r = i >> 2, c2 = i & 3;
            cpa16(smb + SB_B2H + r * 80 + c2 * 16, s3 + r * 64 + c2 * 16);
            cpa16(smb + SB_B2L + r * 80 + c2 * 16, s4 + r * 64 + c2 * 16);
        }
        cpa_commit();
    }

    // ---- stats butterfly (registers only)
    float uv[2][2], rv[2][2];
#pragma unroll
    for (int t = 0; t < 2; t++)
#pragma unroll
        for (int p = 0; p < 2; p++) {
            float a1 = s1v[t][p], a2 = s2v[t][p];
            a1 += __shfl_xor_sync(0xffffffffu, a1, 1);
            a1 += __shfl_xor_sync(0xffffffffu, a1, 2);
            a2 += __shfl_xor_sync(0xffffffffu, a2, 1);
            a2 += __shfl_xor_sync(0xffffffffu, a2, 2);
            float u = a1 * (1.0f / 256.0f);
            uv[t][p] = u;
            rv[t][p] = rsqrtf(a2 * (1.0f / 256.0f) - u * u + 1e-6f);
        }

    // ---- LN correction + quad-shfl softmax + A2 pack, all in registers
    uint32_t A2H[2][2][4], A2L[2][2][4];
    {
        const float* cs = (const float*)(smc + SB_CS);
        const float* bi = (const float*)(smc + SB_BIAS);
#pragma unroll
        for (int t = 0; t < 2; t++) {
#pragma unroll
            for (int nb = 0; nb < 4; nb++) {
                int n = nb * 8 + 2 * tg;
                float c0 = cs[n], c1 = cs[n + 1];
                float b0 = bi[n], b1 = bi[n + 1];
                d1[t][nb][0] = (d1[t][nb][0] - uv[t][0] * c0) * rv[t][0] + b0;
                d1[t][nb][1] = (d1[t][nb][1] - uv[t][0] * c1) * rv[t][0] + b1;
                d1[t][nb][2] = (d1[t][nb][2] - uv[t][1] * c0) * rv[t][1] + b0;
                d1[t][nb][3] = (d1[t][nb][3] - uv[t][1] * c1) * rv[t][1] + b1;
#pragma unroll
                for (int p = 0; p < 2; p++) {
                    float v0 = d1[t][nb][2 * p], v1 = d1[t][nb][2 * p + 1];
                    float m = fmaxf(v0, v1);
                    m = fmaxf(m, __shfl_xor_sync(0xffffffffu, m, 1));
                    m = fmaxf(m, __shfl_xor_sync(0xffffffffu, m, 2));
                    float e0 = __expf(v0 - m), e1 = __expf(v1 - m);
                    float ss = e0 + e1;
                    ss += __shfl_xor_sync(0xffffffffu, ss, 1);
                    ss += __shfl_xor_sync(0xffffffffu, ss, 2);
                    float inv = 1.0f / ss;
                    d1[t][nb][2 * p]     = e0 * inv;
                    d1[t][nb][2 * p + 1] = e1 * inv;
                }
            }
#pragma unroll
            for (int kc = 0; kc < 2; kc++) {
#pragma unroll
                for (int hh = 0; hh < 2; hh++) {
                    const float* dd = d1[t][kc * 2 + hh];
#pragma unroll
                    for (int rr = 0; rr < 2; rr++) {
                        float x0 = dd[2 * rr], x1 = dd[2 * rr + 1];
                        uint32_t hp = bf16pack(x0, x1);
                        float r0 = x0 - __uint_as_float(hp << 16);
                        float r1 = x1 - __uint_as_float(hp & 0xffff0000u);
                        A2H[t][kc][hh * 2 + rr] = hp;
                        A2L[t][kc][hh * 2 + rr] = bf16pack(r0, r1);
                    }
                }
            }
        }
    }
    cpa_wait0();           // B2 resident
    __syncthreads();       // B2 visible; B1/stage region free

    // ---- GEMM2 + staged coalesced stores (8 rounds of 32 outputs)
    const uint32_t* b2h = (const uint32_t*)(smc + SB_B2H);
    const uint32_t* b2l = (const uint32_t*)(smc + SB_B2L);
    float* stg = (float*)(smc + SB_R2);
    float* ob = out + (size_t)b * (C * NPOS) + n0;
    for (int go = 0; go < 8; go++) {
        float d2[2][4][4] = {};
#pragma unroll
        for (int nb = 0; nb < 4; nb++) {
            int n = go * 32 + nb * 8 + g;
#pragma unroll
            for (int kc = 0; kc < 2; kc++) {
                // hoisted B2 fragments (independent of t)
                uint32_t bh[2] = { b2h[n * 20 + kc * 8 + tg], b2h[n * 20 + kc * 8 + tg + 4] };
                uint32_t bl[2] = { b2l[n * 20 + kc * 8 + tg], b2l[n * 20 + kc * 8 + tg + 4] };
#pragma unroll
                for (int t = 0; t < 2; t++) {
                    mma16816(d2[t][nb], A2H[t][kc], bh);
                    mma16816(d2[t][nb], A2L[t][kc], bh);
                    mma16816(d2[t][nb], A2H[t][kc], bl);
                }
            }
        }
        if (go) __syncthreads();   // prior round's stage reads complete
#pragma unroll
        for (int t = 0; t < 2; t++)
#pragma unroll
            for (int nb = 0; nb < 4; nb++) {
                int ol = nb * 8 + 2 * tg;
                int m = w * 32 + t * 16 + g;
                stg[ol * 260 + m]           = d2[t][nb][0];
                stg[(ol + 1) * 260 + m]     = d2[t][nb][1];
                stg[ol * 260 + m + 8]       = d2[t][nb][2];
                stg[(ol + 1) * 260 + m + 8] = d2[t][nb][3];
            }
        __syncthreads();
#pragma unroll
        for (int it = 0; it < 8; it++) {
            int idx = tid + it * 256;
            int row = idx >> 6, c4 = idx & 63;
            float4 v = *reinterpret_cast<const float4*>(stg + row * 260 + c4 * 4);
            *reinterpret_cast<float4*>(ob + (size_t)(go * 32 + row) * NPOS + c4 * 4) = v;
        }
    }
}

// ---------------------------------------------------------------------------
extern "C" void kernel_launch(void* const* d_in, const int* in_sizes, int n_in,
                              void* d_out, int out_size) {
    const float* x2     = (const float*)d_in[0];
    const float* x1_low = (const float*)d_in[1];
    const float* q_w    = (const float*)d_in[2];
    const float* k_w    = (const float*)d_in[3];
    const float* v_w    = (const float*)d_in[4];
    const float* dw_w   = (const float*)d_in[5];
    const float* proj_w = (const float*)d_in[6];
    const float* nq_w   = (const float*)d_in[7];
    const float* nq_b   = (const float*)d_in[8];
    const float* nkv_w  = (const float*)d_in[9];
    const float* nkv_b  = (const float*)d_in[10];
    float* out = (float*)d_out;

    cudaFuncSetAttribute(k_main, cudaFuncAttributeMaxDynamicSharedMemorySize, SB_TOT);

    k_tokens<<<256, 256>>>(x1_low, dw_w);
    k_kvf<<<64, 256>>>(k_w, v_w, q_w, nkv_w, nkv_b, nq_w, nq_b);
    k_foldB<<<256, 256>>>(proj_w);
    k_main<<<256, 256, SB_TOT>>>(x2, out);
}